// round 6
// baseline (speedup 1.0000x reference)
#include <cuda_runtime.h>
#include <cuda_bf16.h>
#include <cstdint>
#include <math.h>

#define BB 2
#define SS 4096
#define DD 1024
#define HH 16
#define BLKSZ 64
#define NB 64          // S / BLK
#define NGB 2          // G / BLK
#define HDIM 64        // D / H
#define MROWS (BB*SS)  // 8192

// ---------------------------------------------------------------------------
// Device scratch (no allocation allowed)
// ---------------------------------------------------------------------------
__device__ __nv_bfloat16 g_x_hi[(size_t)MROWS*DD];
__device__ __nv_bfloat16 g_x_lo[(size_t)MROWS*DD];
__device__ __nv_bfloat16 g_c_hi[(size_t)MROWS*DD];
__device__ __nv_bfloat16 g_c_lo[(size_t)MROWS*DD];
__device__ __nv_bfloat16 g_w_hi[(size_t)4*DD*DD];   // [w][k][n] (native layout)
__device__ __nv_bfloat16 g_w_lo[(size_t)4*DD*DD];
// Q/K/V head-split bf16 hi/lo: [b,h,s,64]
__device__ __nv_bfloat16 g_qh[(size_t)BB*HH*SS*HDIM];
__device__ __nv_bfloat16 g_ql[(size_t)BB*HH*SS*HDIM];
__device__ __nv_bfloat16 g_kh[(size_t)BB*HH*SS*HDIM];
__device__ __nv_bfloat16 g_kl[(size_t)BB*HH*SS*HDIM];
__device__ __nv_bfloat16 g_vh[(size_t)BB*HH*SS*HDIM];
__device__ __nv_bfloat16 g_vl[(size_t)BB*HH*SS*HDIM];
// split-KV partials for heavy q-blocks
__device__ float g_po[(size_t)512*4096];
__device__ float g_pm[512*64];
__device__ float g_pl[512*64];

// ---------------------------------------------------------------------------
// mma.sync / ldmatrix / cp.async helpers (generic sm_80+ PTX)
// ---------------------------------------------------------------------------
__device__ __forceinline__ uint32_t smem_u32(const void* p) {
    uint32_t a;
    asm("{ .reg .u64 t; cvta.to.shared.u64 t, %1; cvt.u32.u64 %0, t; }" : "=r"(a) : "l"(p));
    return a;
}
__device__ __forceinline__ void ldsm_x4(uint32_t* r, uint32_t addr) {
    asm volatile("ldmatrix.sync.aligned.m8n8.x4.shared.b16 {%0,%1,%2,%3}, [%4];"
        : "=r"(r[0]), "=r"(r[1]), "=r"(r[2]), "=r"(r[3]) : "r"(addr));
}
__device__ __forceinline__ void ldsm_x4_trans(uint32_t* r, uint32_t addr) {
    asm volatile("ldmatrix.sync.aligned.m8n8.x4.trans.shared.b16 {%0,%1,%2,%3}, [%4];"
        : "=r"(r[0]), "=r"(r[1]), "=r"(r[2]), "=r"(r[3]) : "r"(addr));
}
__device__ __forceinline__ void ldsm_x2_trans(uint32_t* r, uint32_t addr) {
    asm volatile("ldmatrix.sync.aligned.m8n8.x2.trans.shared.b16 {%0,%1}, [%2];"
        : "=r"(r[0]), "=r"(r[1]) : "r"(addr));
}
__device__ __forceinline__ void mma_bf16(float (&c)[4], const uint32_t* a,
                                         uint32_t b0, uint32_t b1) {
    asm volatile("mma.sync.aligned.m16n8k16.row.col.f32.bf16.bf16.f32 "
        "{%0,%1,%2,%3}, {%4,%5,%6,%7}, {%8,%9}, {%0,%1,%2,%3};"
        : "+f"(c[0]), "+f"(c[1]), "+f"(c[2]), "+f"(c[3])
        : "r"(a[0]), "r"(a[1]), "r"(a[2]), "r"(a[3]), "r"(b0), "r"(b1));
}
__device__ __forceinline__ void cp_async16(uint32_t saddr, const void* gptr) {
    asm volatile("cp.async.cg.shared.global [%0], [%1], 16;" :: "r"(saddr), "l"(gptr));
}
#define CP_COMMIT asm volatile("cp.async.commit_group;")
#define CP_WAIT1  asm volatile("cp.async.wait_group 1;")
#define CP_WAIT0  asm volatile("cp.async.wait_group 0;")

// pack two floats -> bf16x2 hi, bf16x2 lo (residual)
__device__ __forceinline__ uint32_t pack_hilo(float a, float b, uint32_t& lo_out) {
    __nv_bfloat162 h; h.x = __float2bfloat16(a); h.y = __float2bfloat16(b);
    __nv_bfloat162 l;
    l.x = __float2bfloat16(a - __bfloat162float(h.x));
    l.y = __float2bfloat16(b - __bfloat162float(h.y));
    lo_out = *(uint32_t*)&l;
    return *(uint32_t*)&h;
}

// ---------------------------------------------------------------------------
// Split tokens into bf16 hi/lo
// ---------------------------------------------------------------------------
__global__ __launch_bounds__(256) void split_x_kernel(const float* __restrict__ X)
{
    size_t i = (size_t)blockIdx.x * 256 + threadIdx.x;
    float4 v = ((const float4*)X)[i];
    float vs[4] = {v.x, v.y, v.z, v.w};
#pragma unroll
    for (int j = 0; j < 4; j++) {
        __nv_bfloat16 hi = __float2bfloat16(vs[j]);
        float lo = vs[j] - __bfloat162float(hi);
        g_x_hi[i * 4 + j] = hi;
        g_x_lo[i * 4 + j] = __float2bfloat16(lo);
    }
}

// ---------------------------------------------------------------------------
// Elementwise weight split
// ---------------------------------------------------------------------------
__global__ __launch_bounds__(256) void wsplit_kernel(
    const float* __restrict__ Wq, const float* __restrict__ Wk,
    const float* __restrict__ Wv, const float* __restrict__ Wu)
{
    const int w = blockIdx.y;
    const float* W = (w == 0) ? Wq : (w == 1) ? Wk : (w == 2) ? Wv : Wu;
    size_t i = (size_t)blockIdx.x * 256 + threadIdx.x;
    float4 v = ((const float4*)W)[i];
    float vs[4] = {v.x, v.y, v.z, v.w};
    size_t base = (size_t)w * DD * DD + i * 4;
#pragma unroll
    for (int j = 0; j < 4; j++) {
        __nv_bfloat16 hi = __float2bfloat16(vs[j]);
        float lo = vs[j] - __bfloat162float(hi);
        g_w_hi[base + j] = hi;
        g_w_lo[base + j] = __float2bfloat16(lo);
    }
}

// ---------------------------------------------------------------------------
// Split-bf16 HMMA GEMM, 3-stage cp.async pipeline, 1 sync per chunk.
// CTA 128x128, K-chunk 32. mode 0/1/2: bf16 hi/lo q/k/v; mode 3: fp32 + bias.
// ---------------------------------------------------------------------------
#define GK 32
#define SA2 40            // A stride (b16): 32 + 8 pad
#define SB2 136           // B stride (b16)
#define SA_HI_B 0
#define SA_LO_B 10240     // 128*40*2
#define SB_HI_B 20480
#define SB_LO_B 29184
#define STAGE_B 37888
#define NSTAGE 3
#define GEMM_SMEM_BYTES (NSTAGE*STAGE_B)

__global__ __launch_bounds__(256, 2) void gemm_hmma_kernel(
    int mode_base, const float* __restrict__ bias, float* __restrict__ out_ptr)
{
    extern __shared__ __align__(16) char gsm[];
    const uint32_t smem_base = smem_u32(gsm);

    const int t    = threadIdx.x;
    const int lane = t & 31;
    const int wid  = t >> 5;
    const int wm   = wid & 3;
    const int wn   = wid >> 2;
    const int mode = mode_base + blockIdx.z;

    const int n0 = blockIdx.x * 128;
    const int m0 = blockIdx.y * 128;

    const __nv_bfloat16* Ahi = (mode < 3) ? g_x_hi : g_c_hi;
    const __nv_bfloat16* Alo = (mode < 3) ? g_x_lo : g_c_lo;
    const __nv_bfloat16* Bhi = g_w_hi + (size_t)mode * DD * DD;
    const __nv_bfloat16* Blo = g_w_lo + (size_t)mode * DD * DD;

    float acc[2][8][4];
#pragma unroll
    for (int mi = 0; mi < 2; mi++)
#pragma unroll
        for (int nj = 0; nj < 8; nj++)
#pragma unroll
            for (int e = 0; e < 4; e++) acc[mi][nj][e] = 0.f;

    const int lrow = lane & 15;
    const int lcol = (lane >> 4) * 8;

    const int arow0 = t >> 2,          aseg0 = (t & 3) * 8;
    const int arow1 = (t + 256) >> 2,  aseg1 = ((t + 256) & 3) * 8;
    const int brow0 = t >> 4,          bseg0 = (t & 15) * 8;
    const int brow1 = (t + 256) >> 4,  bseg1 = ((t + 256) & 15) * 8;

#define GEMM_PREFETCH(KC, SBUF) do {                                        \
    const int k0_ = (KC) * GK;                                              \
    const uint32_t sb_ = smem_base + (SBUF);                                \
    {   size_t go = (size_t)(m0 + arow0) * DD + k0_ + aseg0;                \
        uint32_t so = sb_ + (uint32_t)(arow0 * SA2 + aseg0) * 2;            \
        cp_async16(so + SA_HI_B, Ahi + go);                                 \
        cp_async16(so + SA_LO_B, Alo + go); }                               \
    {   size_t go = (size_t)(m0 + arow1) * DD + k0_ + aseg1;                \
        uint32_t so = sb_ + (uint32_t)(arow1 * SA2 + aseg1) * 2;            \
        cp_async16(so + SA_HI_B, Ahi + go);                                 \
        cp_async16(so + SA_LO_B, Alo + go); }                               \
    {   size_t go = (size_t)(k0_ + brow0) * DD + n0 + bseg0;                \
        uint32_t so = sb_ + (uint32_t)(brow0 * SB2 + bseg0) * 2;            \
        cp_async16(so + SB_HI_B, Bhi + go);                                 \
        cp_async16(so + SB_LO_B, Blo + go); }                               \
    {   size_t go = (size_t)(k0_ + brow1) * DD + n0 + bseg1;                \
        uint32_t so = sb_ + (uint32_t)(brow1 * SB2 + bseg1) * 2;            \
        cp_async16(so + SB_HI_B, Bhi + go);                                 \
        cp_async16(so + SB_LO_B, Blo + go); }                               \
    CP_COMMIT; } while (0)

    GEMM_PREFETCH(0, 0);
    GEMM_PREFETCH(1, STAGE_B);

    int cs = 0;          // compute-stage buffer offset index
    int ps = 2;          // prefetch buffer index for kc+2
    for (int kc = 0; kc < 32; kc++) {
        if (kc <= 29) { CP_WAIT1; } else { CP_WAIT0; }
        __syncthreads();
        if (kc + 2 < 32) {
            GEMM_PREFETCH(kc + 2, (uint32_t)(ps * STAGE_B));
            ps = (ps + 1 == NSTAGE) ? 0 : ps + 1;
        }

        const uint32_t sb = smem_base + (uint32_t)(cs * STAGE_B);
        cs = (cs + 1 == NSTAGE) ? 0 : cs + 1;
#pragma unroll
        for (int kk = 0; kk < 2; kk++) {
            uint32_t ah[2][4], al[2][4];
#pragma unroll
            for (int mi = 0; mi < 2; mi++) {
                uint32_t off = (uint32_t)((wm * 32 + mi * 16 + lrow) * SA2 + kk * 16 + lcol) * 2;
                ldsm_x4(ah[mi], sb + SA_HI_B + off);
                ldsm_x4(al[mi], sb + SA_LO_B + off);
            }
            // B via x4.trans: one load = two n8 frags (lanes 16-31 -> col+8)
            uint32_t bh[8][2], bl[8][2];
#pragma unroll
            for (int njp = 0; njp < 4; njp++) {
                uint32_t off = (uint32_t)((kk * 16 + lrow) * SB2
                               + wn * 64 + njp * 16 + (lane >> 4) * 8) * 2;
                uint32_t r4[4];
                ldsm_x4_trans(r4, sb + SB_HI_B + off);
                bh[2*njp][0] = r4[0]; bh[2*njp][1] = r4[1];
                bh[2*njp+1][0] = r4[2]; bh[2*njp+1][1] = r4[3];
                ldsm_x4_trans(r4, sb + SB_LO_B + off);
                bl[2*njp][0] = r4[0]; bl[2*njp][1] = r4[1];
                bl[2*njp+1][0] = r4[2]; bl[2*njp+1][1] = r4[3];
            }
#pragma unroll
            for (int mi = 0; mi < 2; mi++)
#pragma unroll
                for (int nj = 0; nj < 8; nj++) {
                    mma_bf16(acc[mi][nj], ah[mi], bh[nj][0], bh[nj][1]);
                    mma_bf16(acc[mi][nj], ah[mi], bl[nj][0], bl[nj][1]);
                    mma_bf16(acc[mi][nj], al[mi], bh[nj][0], bh[nj][1]);
                }
        }
    }
    __syncthreads();

    // Epilogue
#pragma unroll
    for (int mi = 0; mi < 2; mi++) {
        const int r0 = m0 + wm * 32 + mi * 16 + (lane >> 2);
#pragma unroll
        for (int nj = 0; nj < 8; nj++) {
            const int col = wn * 64 + nj * 8 + (lane & 3) * 2;
            if (mode < 3) {
                __nv_bfloat16* Oh = (mode == 0) ? g_qh : (mode == 1) ? g_kh : g_vh;
                __nv_bfloat16* Ol = (mode == 0) ? g_ql : (mode == 1) ? g_kl : g_vl;
                const int h  = (n0 + col) >> 6;
                const int dd = col & 63;
#pragma unroll
                for (int half = 0; half < 2; half++) {
                    int r = r0 + half * 8;
                    int b_ = r >> 12, s = r & 4095;
                    float a0 = acc[mi][nj][half * 2 + 0];
                    float a1 = acc[mi][nj][half * 2 + 1];
                    uint32_t lo, hi = pack_hilo(a0, a1, lo);
                    size_t idx = (((size_t)(b_ * HH + h)) * SS + s) * HDIM + dd;
                    *(uint32_t*)(Oh + idx) = hi;
                    *(uint32_t*)(Ol + idx) = lo;
                }
            } else {
                float bv0 = bias[n0 + col], bv1 = bias[n0 + col + 1];
                float2 st0; st0.x = acc[mi][nj][0] + bv0; st0.y = acc[mi][nj][1] + bv1;
                float2 st1; st1.x = acc[mi][nj][2] + bv0; st1.y = acc[mi][nj][3] + bv1;
                *(float2*)(out_ptr + (size_t)r0 * DD + n0 + col) = st0;
                *(float2*)(out_ptr + (size_t)(r0 + 8) * DD + n0 + col) = st1;
            }
        }
    }
}

// ---------------------------------------------------------------------------
// BigBird sparse attention on HMMA + split-KV for heavy q-blocks.
// ---------------------------------------------------------------------------
#define ATT_STRB 144                  // 72 b16 row stride, in bytes
#define T_KH 0
#define T_KL 9216
#define T_VH 18432
#define T_VL 27648
#define T_QH 36864
#define T_QL 46080
#define T_PEN2 36864                  // float[64][68], overlays Q area
#define T_PEN1 55296                  // float[64]
#define ATTN_SMEM_BYTES 55552

__global__ __launch_bounds__(128, 3) void attn_kernel(
    const float* __restrict__ band_mask,
    const float* __restrict__ from_mask,
    const float* __restrict__ to_mask)
{
    extern __shared__ __align__(16) char smraw[];
    const uint32_t smem_base = smem_u32(smraw);
    float* pen2d = (float*)(smraw + T_PEN2);
    float* pen1  = (float*)(smraw + T_PEN1);

    const int bx = blockIdx.x;
    const int h  = blockIdx.y;
    const int b  = blockIdx.z;
    const int t  = threadIdx.x;
    const int lane = t & 31;
    const int wid  = t >> 5;

    const bool heavy = (bx >= 62);
    int qb, ch = 0;
    if (heavy) { int hx = bx - 62; qb = hx >> 3; ch = hx & 7; }
    else qb = bx + 2;

    const float rs  = 0.125f;
    const float pen = -10000.f;
    const size_t bh64 = ((size_t)(b * HH + h)) * SS * HDIM;

    // ---- Load Q tile (hi/lo) into staging area ----
    {
        const __nv_bfloat16* qhp = g_qh + bh64 + (size_t)qb * BLKSZ * HDIM;
        const __nv_bfloat16* qlp = g_ql + bh64 + (size_t)qb * BLKSZ * HDIM;
        for (int i = t; i < 512; i += 128) {
            int row = i >> 3, seg = (i & 7) * 8;
            *(uint4*)(smraw + T_QH + row * ATT_STRB + seg * 2) = *(const uint4*)(qhp + row * HDIM + seg);
            *(uint4*)(smraw + T_QL + row * ATT_STRB + seg * 2) = *(const uint4*)(qlp + row * HDIM + seg);
        }
    }
    __syncthreads();

    uint32_t qfh[4][4], qfl[4][4];
    {
        const int lrow = lane & 15;
        const int lcol = (lane >> 4) * 8;
#pragma unroll
        for (int kk = 0; kk < 4; kk++) {
            uint32_t off = (uint32_t)((wid * 16 + lrow) * ATT_STRB + (kk * 16 + lcol) * 2);
            ldsm_x4(qfh[kk], smem_base + T_QH + off);
            ldsm_x4(qfl[kk], smem_base + T_QL + off);
        }
    }
    __syncthreads();   // everyone done reading Q before pen2d overlays it

    // ---- schedule ----
    int nt;
    int kbs[5];
    bool is_band = false;
    if (heavy) {
        nt = 8;
    } else if (qb == NGB) {
        nt = 5; kbs[0]=0; kbs[1]=1; kbs[2]=2; kbs[3]=3; kbs[4]=4;
    } else if (qb == NB - 1) {
        nt = 5; kbs[0]=0; kbs[1]=1; kbs[2]=61; kbs[3]=62; kbs[4]=63;
    } else {
        nt = 5; kbs[0]=0; kbs[1]=1; kbs[2]=qb-1; kbs[3]=qb; kbs[4]=qb+1; is_band = true;
    }

    float m0 = -1e30f, m1 = -1e30f, l0 = 0.f, l1 = 0.f;
    float o[8][4];
#pragma unroll
    for (int nj = 0; nj < 8; nj++)
#pragma unroll
        for (int e = 0; e < 4; e++) o[nj][e] = 0.f;

    for (int it = 0; it < nt; it++) {
        const int kb = heavy ? (ch * 8 + it) : kbs[it];
        const bool band_tile = (is_band && it >= 2);

        // ---- Fill K/V hi/lo tiles ----
        {
            const __nv_bfloat16* khp = g_kh + bh64 + (size_t)kb * BLKSZ * HDIM;
            const __nv_bfloat16* klp = g_kl + bh64 + (size_t)kb * BLKSZ * HDIM;
            const __nv_bfloat16* vhp = g_vh + bh64 + (size_t)kb * BLKSZ * HDIM;
            const __nv_bfloat16* vlp = g_vl + bh64 + (size_t)kb * BLKSZ * HDIM;
            for (int i = t; i < 512; i += 128) {
                int row = i >> 3, seg = (i & 7) * 8;
                int so = row * ATT_STRB + seg * 2, go = row * HDIM + seg;
                *(uint4*)(smraw + T_KH + so) = *(const uint4*)(khp + go);
                *(uint4*)(smraw + T_KL + so) = *(const uint4*)(klp + go);
                *(uint4*)(smraw + T_VH + so) = *(const uint4*)(vhp + go);
                *(uint4*)(smraw + T_VL + so) = *(const uint4*)(vlp + go);
            }
        }
        // ---- Fill penalty tiles ----
        if (band_tile) {
            const float* bmb = band_mask
                + ((size_t)(b * 60 + (qb - 3)) * 64) * 192 + (size_t)(it - 2) * 64;
            for (int i = t; i < 1024; i += 128) {
                int row = i >> 4, c4 = (i & 15) * 4;
                float4 mv = *(const float4*)(bmb + row * 192 + c4);
                float* d = pen2d + row * 68 + c4;
                d[0] = (1.f - mv.x) * pen; d[1] = (1.f - mv.y) * pen;
                d[2] = (1.f - mv.z) * pen; d[3] = (1.f - mv.w) * pen;
            }
        } else {
            if (t < 16) {
                float4 mv = *(const float4*)(to_mask + (size_t)b * SS + kb * BLKSZ + t * 4);
                pen1[t*4+0] = (1.f - mv.x) * pen; pen1[t*4+1] = (1.f - mv.y) * pen;
                pen1[t*4+2] = (1.f - mv.z) * pen; pen1[t*4+3] = (1.f - mv.w) * pen;
            }
        }
        __syncthreads();

        // ---- Scores: S = Q K^T (split precision) ----
        float acc[8][4];
#pragma unroll
        for (int nj = 0; nj < 8; nj++)
#pragma unroll
            for (int e = 0; e < 4; e++) acc[nj][e] = 0.f;

#pragma unroll
        for (int nj = 0; nj < 8; nj++) {
            uint32_t kh8[8], kl8[8];
            uint32_t rbase = (uint32_t)((nj * 8 + (lane & 7)) * ATT_STRB + (lane >> 3) * 16);
            ldsm_x4(kh8,     smem_base + T_KH + rbase);
            ldsm_x4(kh8 + 4, smem_base + T_KH + rbase + 64);
            ldsm_x4(kl8,     smem_base + T_KL + rbase);
            ldsm_x4(kl8 + 4, smem_base + T_KL + rbase + 64);
#pragma unroll
            for (int kk = 0; kk < 4; kk++) {
                mma_bf16(acc[nj], qfh[kk], kh8[2*kk], kh8[2*kk+1]);
                mma_bf16(acc[nj], qfh[kk], kl8[2*kk], kl8[2*kk+1]);
                mma_bf16(acc[nj], qfl[kk], kh8[2*kk], kh8[2*kk+1]);
            }
        }

        // ---- Scale + mask ----
        const int qr0 = wid * 16 + (lane >> 2);
#pragma unroll
        for (int nj = 0; nj < 8; nj++) {
#pragma unroll
            for (int e = 0; e < 4; e++) {
                int col = nj * 8 + (lane & 3) * 2 + (e & 1);
                float pe = band_tile
                    ? pen2d[(qr0 + (e >> 1) * 8) * 68 + col]
                    : pen1[col];
                acc[nj][e] = acc[nj][e] * rs + pe;
            }
        }

        // ---- Streaming softmax ----
        float tm0 = -1e30f, tm1 = -1e30f;
#pragma unroll
        for (int nj = 0; nj < 8; nj++) {
            tm0 = fmaxf(tm0, fmaxf(acc[nj][0], acc[nj][1]));
            tm1 = fmaxf(tm1, fmaxf(acc[nj][2], acc[nj][3]));
        }
        tm0 = fmaxf(tm0, __shfl_xor_sync(0xffffffffu, tm0, 1));
        tm0 = fmaxf(tm0, __shfl_xor_sync(0xffffffffu, tm0, 2));
        tm1 = fmaxf(tm1, __shfl_xor_sync(0xffffffffu, tm1, 1));
        tm1 = fmaxf(tm1, __shfl_xor_sync(0xffffffffu, tm1, 2));

        float nm0 = fmaxf(m0, tm0), nm1 = fmaxf(m1, tm1);
        float c0 = __expf(m0 - nm0), c1 = __expf(m1 - nm1);
        float ts0 = 0.f, ts1 = 0.f;
#pragma unroll
        for (int nj = 0; nj < 8; nj++) {
            acc[nj][0] = __expf(acc[nj][0] - nm0);
            acc[nj][1] = __expf(acc[nj][1] - nm0);
            acc[nj][2] = __expf(acc[nj][2] - nm1);
            acc[nj][3] = __expf(acc[nj][3] - nm1);
            ts0 += acc[nj][0] + acc[nj][1];
            ts1 += acc[nj][2] + acc[nj][3];
        }
        ts0 += __shfl_xor_sync(0xffffffffu, ts0, 1);
        ts0 += __shfl_xor_sync(0xffffffffu, ts0, 2);
        ts1 += __shfl_xor_sync(0xffffffffu, ts1, 1);
        ts1 += __shfl_xor_sync(0xffffffffu, ts1, 2);
        l0 = l0 * c0 + ts0;  l1 = l1 * c1 + ts1;
        m0 = nm0;  m1 = nm1;
#pragma unroll
        for (int nj = 0; nj < 8; nj++) {
            o[nj][0] *= c0; o[nj][1] *= c0;
            o[nj][2] *= c1; o[nj][3] *= c1;
        }

        // ---- Pack P -> A-frags (bf16 hi/lo) ----
        uint32_t phi[4][4], plo[4][4];
#pragma unroll
        for (int kk2 = 0; kk2 < 4; kk2++) {
            phi[kk2][0] = pack_hilo(acc[2*kk2][0],   acc[2*kk2][1],   plo[kk2][0]);
            phi[kk2][1] = pack_hilo(acc[2*kk2][2],   acc[2*kk2][3],   plo[kk2][1]);
            phi[kk2][2] = pack_hilo(acc[2*kk2+1][0], acc[2*kk2+1][1], plo[kk2][2]);
            phi[kk2][3] = pack_hilo(acc[2*kk2+1][2], acc[2*kk2+1][3], plo[kk2][3]);
        }

        // ---- PV: O += P V (split precision), V via x4.trans (2 frags/load) ----
#pragma unroll
        for (int p = 0; p < 8; p += 2) {
#pragma unroll
            for (int kk2 = 0; kk2 < 4; kk2++) {
                uint32_t off = (uint32_t)((kk2 * 16 + (lane & 15)) * ATT_STRB
                               + (p + (lane >> 4)) * 16);
                uint32_t vh4[4], vl4[4];
                ldsm_x4_trans(vh4, smem_base + T_VH + off);
                ldsm_x4_trans(vl4, smem_base + T_VL + off);
                mma_bf16(o[p],   phi[kk2], vh4[0], vh4[1]);
                mma_bf16(o[p],   phi[kk2], vl4[0], vl4[1]);
                mma_bf16(o[p],   plo[kk2], vh4[0], vh4[1]);
                mma_bf16(o[p+1], phi[kk2], vh4[2], vh4[3]);
                mma_bf16(o[p+1], phi[kk2], vl4[2], vl4[3]);
                mma_bf16(o[p+1], plo[kk2], vh4[2], vh4[3]);
            }
        }
        __syncthreads();
    }

    const int r0 = wid * 16 + (lane >> 2);
    if (!heavy) {
        const int s0 = qb * BLKSZ + r0;
        const int s1 = s0 + 8;
        float inv0 = from_mask[(size_t)b * SS + s0] / l0;
        float inv1 = from_mask[(size_t)b * SS + s1] / l1;
#pragma unroll
        for (int njd = 0; njd < 8; njd++) {
            const int col = njd * 8 + (lane & 3) * 2;
            {
                size_t idx = ((size_t)b * SS + s0) * DD + h * HDIM + col;
                uint32_t lo, hi = pack_hilo(o[njd][0] * inv0, o[njd][1] * inv0, lo);
                *(uint32_t*)(g_c_hi + idx) = hi;
                *(uint32_t*)(g_c_lo + idx) = lo;
            }
            {
                size_t idx = ((size_t)b * SS + s1) * DD + h * HDIM + col;
                uint32_t lo, hi = pack_hilo(o[njd][2] * inv1, o[njd][3] * inv1, lo);
                *(uint32_t*)(g_c_hi + idx) = hi;
                *(uint32_t*)(g_c_lo + idx) = lo;
            }
        }
    } else {
        const int cid = ((b * HH + h) * 2 + qb) * 8 + ch;
        float* pob = g_po + (size_t)cid * 4096;
#pragma unroll
        for (int njd = 0; njd < 8; njd++) {
            const int col = njd * 8 + (lane & 3) * 2;
            float2 s0v; s0v.x = o[njd][0]; s0v.y = o[njd][1];
            float2 s1v; s1v.x = o[njd][2]; s1v.y = o[njd][3];
            *(float2*)(pob + r0 * 64 + col) = s0v;
            *(float2*)(pob + (r0 + 8) * 64 + col) = s1v;
        }
        if ((lane & 3) == 0) {
            g_pm[cid * 64 + r0]     = m0;
            g_pm[cid * 64 + r0 + 8] = m1;
            g_pl[cid * 64 + r0]     = l0;
            g_pl[cid * 64 + r0 + 8] = l1;
        }
    }
}

// ---------------------------------------------------------------------------
// Combine split-KV partials for heavy q-blocks.
// ---------------------------------------------------------------------------
__global__ __launch_bounds__(128) void attn_combine(const float* __restrict__ from_mask)
{
    const int x  = blockIdx.x;
    const int qb = x & 1;
    const int h  = (x >> 1) & 15;
    const int b  = x >> 5;
    const int t  = threadIdx.x;
    const int r  = t >> 1;
    const int c0 = (t & 1) * 32;
    const int base8 = x * 8;

    float m[8], l[8], M = -1e30f;
#pragma unroll
    for (int i = 0; i < 8; i++) {
        m[i] = g_pm[(base8 + i) * 64 + r];
        l[i] = g_pl[(base8 + i) * 64 + r];
        M = fmaxf(M, m[i]);
    }
    float L = 0.f, sc[8];
#pragma unroll
    for (int i = 0; i < 8; i++) { sc[i] = __expf(m[i] - M); L += l[i] * sc[i]; }

    float acc[32];
#pragma unroll
    for (int c = 0; c < 32; c++) acc[c] = 0.f;
#pragma unroll
    for (int i = 0; i < 8; i++) {
        const float* p = g_po + (size_t)(base8 + i) * 4096 + r * 64 + c0;
        float s = sc[i];
#pragma unroll
        for (int c4 = 0; c4 < 8; c4++) {
            float4 v = *(const float4*)(p + c4 * 4);
            acc[c4*4+0] += s * v.x; acc[c4*4+1] += s * v.y;
            acc[c4*4+2] += s * v.z; acc[c4*4+3] += s * v.w;
        }
    }

    const int s_ = qb * BLKSZ + r;
    float inv = from_mask[(size_t)b * SS + s_] / L;
    size_t idx = ((size_t)b * SS + s_) * DD + h * HDIM + c0;
#pragma unroll
    for (int c = 0; c < 32; c += 2) {
        uint32_t lo, hi = pack_hilo(acc[c] * inv, acc[c+1] * inv, lo);
        *(uint32_t*)(g_c_hi + idx + c) = hi;
        *(uint32_t*)(g_c_lo + idx + c) = lo;
    }
}

// ---------------------------------------------------------------------------
extern "C" void kernel_launch(void* const* d_in, const int* in_sizes, int n_in,
                              void* d_out, int out_size)
{
    const float* tokens    = (const float*)d_in[0];
    const float* band_mask = (const float*)d_in[1];
    const float* from_mask = (const float*)d_in[2];
    const float* to_mask   = (const float*)d_in[3];
    const float* Wq        = (const float*)d_in[4];
    const float* Wk        = (const float*)d_in[5];
    const float* Wv        = (const float*)d_in[6];
    const float* Wu        = (const float*)d_in[7];
    const float* bu        = (const float*)d_in[8];
    float* out = (float*)d_out;

    cudaFuncSetAttribute(attn_kernel,
                         cudaFuncAttributeMaxDynamicSharedMemorySize, ATTN_SMEM_BYTES);
    cudaFuncSetAttribute(gemm_hmma_kernel,
                         cudaFuncAttributeMaxDynamicSharedMemorySize, GEMM_SMEM_BYTES);

    // 0) Precision-split inputs and weights
    split_x_kernel<<<(MROWS * DD / 4) / 256, 256>>>(tokens);
    wsplit_kernel<<<dim3(1024, 4), 256>>>(Wq, Wk, Wv, Wu);

    // 1) QKV projections (3-stage pipelined HMMA, grid.z = q/k/v)
    gemm_hmma_kernel<<<dim3(8, 64, 3), 256, GEMM_SMEM_BYTES>>>(0, nullptr, nullptr);

    // 2) Sparse attention (light + split-KV heavy in one grid)
    attn_kernel<<<dim3(78, HH, BB), 128, ATTN_SMEM_BYTES>>>(band_mask, from_mask, to_mask);

    // 2b) Combine heavy partials
    attn_combine<<<64, 128>>>(from_mask);

    // 3) Output projection + bias (3-stage pipelined HMMA)
    gemm_hmma_kernel<<<dim3(8, 64, 1), 256, GEMM_SMEM_BYTES>>>(3, bu, out);
}

// round 8
// speedup vs baseline: 1.4545x; 1.4545x over previous
#include <cuda_runtime.h>
#include <cuda_bf16.h>
#include <cstdint>
#include <math.h>

#define BB 2
#define SS 4096
#define DD 1024
#define HH 16
#define BLKSZ 64
#define NB 64          // S / BLK
#define NGB 2          // G / BLK
#define HDIM 64        // D / H
#define MROWS (BB*SS)  // 8192

// ---------------------------------------------------------------------------
// Device scratch (no allocation allowed)
// ---------------------------------------------------------------------------
__device__ __nv_bfloat16 g_x_hi[(size_t)MROWS*DD];
__device__ __nv_bfloat16 g_x_lo[(size_t)MROWS*DD];
__device__ __nv_bfloat16 g_c_hi[(size_t)MROWS*DD];
__device__ __nv_bfloat16 g_c_lo[(size_t)MROWS*DD];
__device__ __nv_bfloat16 g_w_hi[(size_t)4*DD*DD];   // [w][k][n] (native layout)
__device__ __nv_bfloat16 g_w_lo[(size_t)4*DD*DD];
// Q/K/V head-split bf16 hi/lo: [b,h,s,64]
__device__ __nv_bfloat16 g_qh[(size_t)BB*HH*SS*HDIM];
__device__ __nv_bfloat16 g_ql[(size_t)BB*HH*SS*HDIM];
__device__ __nv_bfloat16 g_kh[(size_t)BB*HH*SS*HDIM];
__device__ __nv_bfloat16 g_kl[(size_t)BB*HH*SS*HDIM];
__device__ __nv_bfloat16 g_vh[(size_t)BB*HH*SS*HDIM];
__device__ __nv_bfloat16 g_vl[(size_t)BB*HH*SS*HDIM];
// split-KV partials for heavy q-blocks
__device__ float g_po[(size_t)512*4096];
__device__ float g_pm[512*64];
__device__ float g_pl[512*64];

// ---------------------------------------------------------------------------
// mma.sync / ldmatrix / cp.async helpers (generic sm_80+ PTX)
// ---------------------------------------------------------------------------
__device__ __forceinline__ uint32_t smem_u32(const void* p) {
    uint32_t a;
    asm("{ .reg .u64 t; cvta.to.shared.u64 t, %1; cvt.u32.u64 %0, t; }" : "=r"(a) : "l"(p));
    return a;
}
__device__ __forceinline__ void ldsm_x4(uint32_t* r, uint32_t addr) {
    asm volatile("ldmatrix.sync.aligned.m8n8.x4.shared.b16 {%0,%1,%2,%3}, [%4];"
        : "=r"(r[0]), "=r"(r[1]), "=r"(r[2]), "=r"(r[3]) : "r"(addr));
}
__device__ __forceinline__ void ldsm_x2_trans(uint32_t* r, uint32_t addr) {
    asm volatile("ldmatrix.sync.aligned.m8n8.x2.trans.shared.b16 {%0,%1}, [%2];"
        : "=r"(r[0]), "=r"(r[1]) : "r"(addr));
}
__device__ __forceinline__ void mma_bf16(float (&c)[4], const uint32_t* a,
                                         uint32_t b0, uint32_t b1) {
    asm volatile("mma.sync.aligned.m16n8k16.row.col.f32.bf16.bf16.f32 "
        "{%0,%1,%2,%3}, {%4,%5,%6,%7}, {%8,%9}, {%0,%1,%2,%3};"
        : "+f"(c[0]), "+f"(c[1]), "+f"(c[2]), "+f"(c[3])
        : "r"(a[0]), "r"(a[1]), "r"(a[2]), "r"(a[3]), "r"(b0), "r"(b1));
}
__device__ __forceinline__ void cp_async16(uint32_t saddr, const void* gptr) {
    asm volatile("cp.async.cg.shared.global [%0], [%1], 16;" :: "r"(saddr), "l"(gptr));
}
#define CP_COMMIT asm volatile("cp.async.commit_group;")
#define CP_WAIT2  asm volatile("cp.async.wait_group 2;")
#define CP_WAIT1  asm volatile("cp.async.wait_group 1;")
#define CP_WAIT0  asm volatile("cp.async.wait_group 0;")

// pack two floats -> bf16x2 hi, bf16x2 lo (residual)
__device__ __forceinline__ uint32_t pack_hilo(float a, float b, uint32_t& lo_out) {
    __nv_bfloat162 h; h.x = __float2bfloat16(a); h.y = __float2bfloat16(b);
    __nv_bfloat162 l;
    l.x = __float2bfloat16(a - __bfloat162float(h.x));
    l.y = __float2bfloat16(b - __bfloat162float(h.y));
    lo_out = *(uint32_t*)&l;
    return *(uint32_t*)&h;
}

// ---------------------------------------------------------------------------
// Split tokens into bf16 hi/lo
// ---------------------------------------------------------------------------
__global__ __launch_bounds__(256) void split_x_kernel(const float* __restrict__ X)
{
    size_t i = (size_t)blockIdx.x * 256 + threadIdx.x;
    float4 v = ((const float4*)X)[i];
    float vs[4] = {v.x, v.y, v.z, v.w};
#pragma unroll
    for (int j = 0; j < 4; j++) {
        __nv_bfloat16 hi = __float2bfloat16(vs[j]);
        float lo = vs[j] - __bfloat162float(hi);
        g_x_hi[i * 4 + j] = hi;
        g_x_lo[i * 4 + j] = __float2bfloat16(lo);
    }
}

// ---------------------------------------------------------------------------
// Elementwise weight split
// ---------------------------------------------------------------------------
__global__ __launch_bounds__(256) void wsplit_kernel(
    const float* __restrict__ Wq, const float* __restrict__ Wk,
    const float* __restrict__ Wv, const float* __restrict__ Wu)
{
    const int w = blockIdx.y;
    const float* W = (w == 0) ? Wq : (w == 1) ? Wk : (w == 2) ? Wv : Wu;
    size_t i = (size_t)blockIdx.x * 256 + threadIdx.x;
    float4 v = ((const float4*)W)[i];
    float vs[4] = {v.x, v.y, v.z, v.w};
    size_t base = (size_t)w * DD * DD + i * 4;
#pragma unroll
    for (int j = 0; j < 4; j++) {
        __nv_bfloat16 hi = __float2bfloat16(vs[j]);
        float lo = vs[j] - __bfloat162float(hi);
        g_w_hi[base + j] = hi;
        g_w_lo[base + j] = __float2bfloat16(lo);
    }
}

// ---------------------------------------------------------------------------
// Split-bf16 HMMA GEMM with cp.async double buffering (R5-proven version).
// CTA 128x128, K-chunk 32, 2 stages. mode 0/1/2: bf16 hi/lo q/k/v;
// mode 3: fp32 out + bias.
// ---------------------------------------------------------------------------
#define GK 32
#define SA2 40            // A stride (b16): 32 + 8 pad
#define SB2 136           // B stride (b16)
#define SA_HI_B 0
#define SA_LO_B 10240     // 128*40*2
#define SB_HI_B 20480
#define SB_LO_B 29184
#define STAGE_B 37888
#define GEMM_SMEM_BYTES (2*STAGE_B)

__global__ __launch_bounds__(256, 2) void gemm_hmma_kernel(
    int mode_base, const float* __restrict__ bias, float* __restrict__ out_ptr)
{
    extern __shared__ __align__(16) char gsm[];
    const uint32_t smem_base = smem_u32(gsm);

    const int t    = threadIdx.x;
    const int lane = t & 31;
    const int wid  = t >> 5;
    const int wm   = wid & 3;
    const int wn   = wid >> 2;
    const int mode = mode_base + blockIdx.z;

    const int n0 = blockIdx.x * 128;
    const int m0 = blockIdx.y * 128;

    const __nv_bfloat16* Ahi = (mode < 3) ? g_x_hi : g_c_hi;
    const __nv_bfloat16* Alo = (mode < 3) ? g_x_lo : g_c_lo;
    const __nv_bfloat16* Bhi = g_w_hi + (size_t)mode * DD * DD;
    const __nv_bfloat16* Blo = g_w_lo + (size_t)mode * DD * DD;

    float acc[2][8][4];
#pragma unroll
    for (int mi = 0; mi < 2; mi++)
#pragma unroll
        for (int nj = 0; nj < 8; nj++)
#pragma unroll
            for (int e = 0; e < 4; e++) acc[mi][nj][e] = 0.f;

    const int lrow = lane & 15;
    const int lcol = (lane >> 4) * 8;

    const int arow0 = t >> 2,          aseg0 = (t & 3) * 8;
    const int arow1 = (t + 256) >> 2,  aseg1 = ((t + 256) & 3) * 8;
    const int brow0 = t >> 4,          bseg0 = (t & 15) * 8;
    const int brow1 = (t + 256) >> 4,  bseg1 = ((t + 256) & 15) * 8;

#define GEMM_PREFETCH(KC) do {                                              \
    const int k0_ = (KC) * GK;                                              \
    const uint32_t sb_ = smem_base + ((KC) & 1) * STAGE_B;                  \
    {   size_t go = (size_t)(m0 + arow0) * DD + k0_ + aseg0;                \
        uint32_t so = sb_ + (uint32_t)(arow0 * SA2 + aseg0) * 2;            \
        cp_async16(so + SA_HI_B, Ahi + go);                                 \
        cp_async16(so + SA_LO_B, Alo + go); }                               \
    {   size_t go = (size_t)(m0 + arow1) * DD + k0_ + aseg1;                \
        uint32_t so = sb_ + (uint32_t)(arow1 * SA2 + aseg1) * 2;            \
        cp_async16(so + SA_HI_B, Ahi + go);                                 \
        cp_async16(so + SA_LO_B, Alo + go); }                               \
    {   size_t go = (size_t)(k0_ + brow0) * DD + n0 + bseg0;                \
        uint32_t so = sb_ + (uint32_t)(brow0 * SB2 + bseg0) * 2;            \
        cp_async16(so + SB_HI_B, Bhi + go);                                 \
        cp_async16(so + SB_LO_B, Blo + go); }                               \
    {   size_t go = (size_t)(k0_ + brow1) * DD + n0 + bseg1;                \
        uint32_t so = sb_ + (uint32_t)(brow1 * SB2 + bseg1) * 2;            \
        cp_async16(so + SB_HI_B, Bhi + go);                                 \
        cp_async16(so + SB_LO_B, Blo + go); }                               \
    CP_COMMIT; } while (0)

    GEMM_PREFETCH(0);

    for (int kc = 0; kc < 32; kc++) {
        if (kc + 1 < 32) { GEMM_PREFETCH(kc + 1); CP_WAIT1; }
        else             { CP_WAIT0; }
        __syncthreads();

        const uint32_t sb = smem_base + (kc & 1) * STAGE_B;
#pragma unroll
        for (int kk = 0; kk < 2; kk++) {
            uint32_t ah[2][4], al[2][4];
#pragma unroll
            for (int mi = 0; mi < 2; mi++) {
                uint32_t off = (uint32_t)((wm * 32 + mi * 16 + lrow) * SA2 + kk * 16 + lcol) * 2;
                ldsm_x4(ah[mi], sb + SA_HI_B + off);
                ldsm_x4(al[mi], sb + SA_LO_B + off);
            }
            uint32_t bh[8][2], bl[8][2];
#pragma unroll
            for (int nj = 0; nj < 8; nj++) {
                uint32_t off = (uint32_t)((kk * 16 + lrow) * SB2 + wn * 64 + nj * 8) * 2;
                ldsm_x2_trans(bh[nj], sb + SB_HI_B + off);
                ldsm_x2_trans(bl[nj], sb + SB_LO_B + off);
            }
#pragma unroll
            for (int mi = 0; mi < 2; mi++)
#pragma unroll
                for (int nj = 0; nj < 8; nj++) {
                    mma_bf16(acc[mi][nj], ah[mi], bh[nj][0], bh[nj][1]);
                    mma_bf16(acc[mi][nj], ah[mi], bl[nj][0], bl[nj][1]);
                    mma_bf16(acc[mi][nj], al[mi], bh[nj][0], bh[nj][1]);
                }
        }
        __syncthreads();
    }

    // Epilogue
#pragma unroll
    for (int mi = 0; mi < 2; mi++) {
        const int r0 = m0 + wm * 32 + mi * 16 + (lane >> 2);
#pragma unroll
        for (int nj = 0; nj < 8; nj++) {
            const int col = wn * 64 + nj * 8 + (lane & 3) * 2;
            if (mode < 3) {
                __nv_bfloat16* Oh = (mode == 0) ? g_qh : (mode == 1) ? g_kh : g_vh;
                __nv_bfloat16* Ol = (mode == 0) ? g_ql : (mode == 1) ? g_kl : g_vl;
                const int h  = (n0 + col) >> 6;
                const int dd = col & 63;
#pragma unroll
                for (int half = 0; half < 2; half++) {
                    int r = r0 + half * 8;
                    int b_ = r >> 12, s = r & 4095;
                    float a0 = acc[mi][nj][half * 2 + 0];
                    float a1 = acc[mi][nj][half * 2 + 1];
                    uint32_t lo, hi = pack_hilo(a0, a1, lo);
                    size_t idx = (((size_t)(b_ * HH + h)) * SS + s) * HDIM + dd;
                    *(uint32_t*)(Oh + idx) = hi;
                    *(uint32_t*)(Ol + idx) = lo;
                }
            } else {
                float bv0 = bias[n0 + col], bv1 = bias[n0 + col + 1];
                float2 st0; st0.x = acc[mi][nj][0] + bv0; st0.y = acc[mi][nj][1] + bv1;
                float2 st1; st1.x = acc[mi][nj][2] + bv0; st1.y = acc[mi][nj][3] + bv1;
                *(float2*)(out_ptr + (size_t)r0 * DD + n0 + col) = st0;
                *(float2*)(out_ptr + (size_t)(r0 + 8) * DD + n0 + col) = st1;
            }
        }
    }
}

// ---------------------------------------------------------------------------
// BigBird sparse attention on HMMA, split-KV heavy blocks, cp.async pipelined:
//   K double-buffered (K(it+1) streams during compute of it)
//   V + raw masks single-buffered (issued at iter head, overlap scores)
// Commit order per iter: [VP(it)], [K(it+1)].
//   wait_group 2 before scores  (K(it) ready)
//   wait_group 1 before mask/PV (V+pen ready)
// ---------------------------------------------------------------------------
#define ATT_STRB 144                  // 72 b16 row stride, in bytes
#define KSTAGE(s) ((s) * 18432)       // per stage: KH +0, KL +9216
#define T_VH 36864
#define T_VL 46080
#define T_PEN2 55296                  // raw band_mask floats, 64 x 68 (stride 272B)
#define T_PEN1 72704                  // raw to_mask slice, 64 floats
#define ATTN_SMEM_BYTES 72976

__global__ __launch_bounds__(128, 3) void attn_kernel(
    const float* __restrict__ band_mask,
    const float* __restrict__ from_mask,
    const float* __restrict__ to_mask)
{
    extern __shared__ __align__(16) char smraw[];
    const uint32_t smem_base = smem_u32(smraw);
    const float* pen2f = (const float*)(smraw + T_PEN2);
    const float* pen1f = (const float*)(smraw + T_PEN1);

    const int bx = blockIdx.x;
    const int h  = blockIdx.y;
    const int b  = blockIdx.z;
    const int t  = threadIdx.x;
    const int lane = t & 31;
    const int wid  = t >> 5;

    const bool heavy = (bx >= 62);
    int qb, ch = 0;
    if (heavy) { int hx = bx - 62; qb = hx >> 3; ch = hx & 7; }
    else qb = bx + 2;

    const float rs  = 0.125f;
    const float pen = -10000.f;
    const size_t bh64 = ((size_t)(b * HH + h)) * SS * HDIM;

    // ---- Load Q tile (hi/lo) into K-stage-0 area, extract frags ----
    {
        const __nv_bfloat16* qhp = g_qh + bh64 + (size_t)qb * BLKSZ * HDIM;
        const __nv_bfloat16* qlp = g_ql + bh64 + (size_t)qb * BLKSZ * HDIM;
        for (int i = t; i < 512; i += 128) {
            int row = i >> 3, seg = (i & 7) * 8;
            *(uint4*)(smraw + row * ATT_STRB + seg * 2)        = *(const uint4*)(qhp + row * HDIM + seg);
            *(uint4*)(smraw + 9216 + row * ATT_STRB + seg * 2) = *(const uint4*)(qlp + row * HDIM + seg);
        }
    }
    __syncthreads();

    uint32_t qfh[4][4], qfl[4][4];
    {
        const int lrow = lane & 15;
        const int lcol = (lane >> 4) * 8;
#pragma unroll
        for (int kk = 0; kk < 4; kk++) {
            uint32_t off = (uint32_t)((wid * 16 + lrow) * ATT_STRB + (kk * 16 + lcol) * 2);
            ldsm_x4(qfh[kk], smem_base + off);
            ldsm_x4(qfl[kk], smem_base + 9216 + off);
        }
    }
    __syncthreads();   // everyone done reading Q before K(0) cp.async overwrites

    // ---- schedule ----
    int nt;
    int kbs[5];
    bool is_band = false;
    if (heavy) {
        nt = 8;
    } else if (qb == NGB) {
        nt = 5; kbs[0]=0; kbs[1]=1; kbs[2]=2; kbs[3]=3; kbs[4]=4;
    } else if (qb == NB - 1) {
        nt = 5; kbs[0]=0; kbs[1]=1; kbs[2]=61; kbs[3]=62; kbs[4]=63;
    } else {
        nt = 5; kbs[0]=0; kbs[1]=1; kbs[2]=qb-1; kbs[3]=qb; kbs[4]=qb+1; is_band = true;
    }

#define KB_OF(IT) (heavy ? (ch * 8 + (IT)) : kbs[(IT)])

    // ---- cp.async issue helpers ----
#define ISSUE_K(KB, STG) do {                                               \
    const __nv_bfloat16* khp_ = g_kh + bh64 + (size_t)(KB) * BLKSZ * HDIM;  \
    const __nv_bfloat16* klp_ = g_kl + bh64 + (size_t)(KB) * BLKSZ * HDIM;  \
    for (int i = t; i < 512; i += 128) {                                    \
        int row = i >> 3, seg = (i & 7) * 8;                                \
        uint32_t so = smem_base + KSTAGE(STG) + row * ATT_STRB + seg * 2;   \
        cp_async16(so,        khp_ + row * HDIM + seg);                     \
        cp_async16(so + 9216, klp_ + row * HDIM + seg);                     \
    }                                                                       \
    CP_COMMIT; } while (0)

#define ISSUE_VP(IT, KB, BANDT) do {                                        \
    const __nv_bfloat16* vhp_ = g_vh + bh64 + (size_t)(KB) * BLKSZ * HDIM;  \
    const __nv_bfloat16* vlp_ = g_vl + bh64 + (size_t)(KB) * BLKSZ * HDIM;  \
    for (int i = t; i < 512; i += 128) {                                    \
        int row = i >> 3, seg = (i & 7) * 8;                                \
        uint32_t so = smem_base + T_VH + row * ATT_STRB + seg * 2;          \
        cp_async16(so,        vhp_ + row * HDIM + seg);                     \
        cp_async16(so + 9216, vlp_ + row * HDIM + seg);                     \
    }                                                                       \
    if (BANDT) {                                                            \
        const float* bmb_ = band_mask                                       \
            + ((size_t)(b * 60 + (qb - 3)) * 64) * 192 + (size_t)((IT) - 2) * 64; \
        for (int i = t; i < 1024; i += 128) {                               \
            int row = i >> 4, c = i & 15;                                   \
            cp_async16(smem_base + T_PEN2 + row * 272 + c * 16,             \
                       bmb_ + row * 192 + c * 4);                           \
        }                                                                   \
    } else if (t < 16) {                                                    \
        cp_async16(smem_base + T_PEN1 + t * 16,                             \
                   to_mask + (size_t)b * SS + (KB) * BLKSZ + t * 4);        \
    }                                                                       \
    CP_COMMIT; } while (0)

    // ---- flash state ----
    float m0 = -1e30f, m1 = -1e30f, l0 = 0.f, l1 = 0.f;
    float o[8][4];
#pragma unroll
    for (int nj = 0; nj < 8; nj++)
#pragma unroll
        for (int e = 0; e < 4; e++) o[nj][e] = 0.f;

    // prologue: K(0) -> stage 0
    ISSUE_K(KB_OF(0), 0);

    for (int it = 0; it < nt; it++) {
        const int kb = KB_OF(it);
        const bool band_tile = (is_band && it >= 2);

        ISSUE_VP(it, kb, band_tile);
        if (it + 1 < nt) {
            ISSUE_K(KB_OF(it + 1), (it + 1) & 1);
            CP_WAIT2;            // K(it) landed (VP(it), K(it+1) may be pending)
        } else {
            CP_WAIT1;            // K(it) landed (VP(it) may be pending)
        }
        __syncthreads();

        // ---- Scores: S = Q K^T (split precision), K from stage it&1 ----
        const uint32_t kst = smem_base + KSTAGE(it & 1);
        float acc[8][4];
#pragma unroll
        for (int nj = 0; nj < 8; nj++)
#pragma unroll
            for (int e = 0; e < 4; e++) acc[nj][e] = 0.f;

#pragma unroll
        for (int nj = 0; nj < 8; nj++) {
            uint32_t kh8[8], kl8[8];
            uint32_t rbase = (uint32_t)((nj * 8 + (lane & 7)) * ATT_STRB + (lane >> 3) * 16);
            ldsm_x4(kh8,     kst + rbase);
            ldsm_x4(kh8 + 4, kst + rbase + 64);
            ldsm_x4(kl8,     kst + 9216 + rbase);
            ldsm_x4(kl8 + 4, kst + 9216 + rbase + 64);
#pragma unroll
            for (int kk = 0; kk < 4; kk++) {
                mma_bf16(acc[nj], qfh[kk], kh8[2*kk], kh8[2*kk+1]);
                mma_bf16(acc[nj], qfh[kk], kl8[2*kk], kl8[2*kk+1]);
                mma_bf16(acc[nj], qfl[kk], kh8[2*kk], kh8[2*kk+1]);
            }
        }

        // ---- V + mask data ready? ----
        if (it + 1 < nt) { CP_WAIT1; } else { CP_WAIT0; }
        __syncthreads();

        // ---- Scale + mask ((1-m)*pen computed inline from raw masks) ----
        const int qr0 = wid * 16 + (lane >> 2);
#pragma unroll
        for (int nj = 0; nj < 8; nj++) {
#pragma unroll
            for (int e = 0; e < 4; e++) {
                int col = nj * 8 + (lane & 3) * 2 + (e & 1);
                float mv = band_tile
                    ? pen2f[(qr0 + (e >> 1) * 8) * 68 + col]
                    : pen1f[col];
                acc[nj][e] = acc[nj][e] * rs + (1.f - mv) * pen;
            }
        }

        // ---- Streaming softmax ----
        float tm0 = -1e30f, tm1 = -1e30f;
#pragma unroll
        for (int nj = 0; nj < 8; nj++) {
            tm0 = fmaxf(tm0, fmaxf(acc[nj][0], acc[nj][1]));
            tm1 = fmaxf(tm1, fmaxf(acc[nj][2], acc[nj][3]));
        }
        tm0 = fmaxf(tm0, __shfl_xor_sync(0xffffffffu, tm0, 1));
        tm0 = fmaxf(tm0, __shfl_xor_sync(0xffffffffu, tm0, 2));
        tm1 = fmaxf(tm1, __shfl_xor_sync(0xffffffffu, tm1, 1));
        tm1 = fmaxf(tm1, __shfl_xor_sync(0xffffffffu, tm1, 2));

        float nm0 = fmaxf(m0, tm0), nm1 = fmaxf(m1, tm1);
        float c0 = __expf(m0 - nm0), c1 = __expf(m1 - nm1);
        float ts0 = 0.f, ts1 = 0.f;
#pragma unroll
        for (int nj = 0; nj < 8; nj++) {
            acc[nj][0] = __expf(acc[nj][0] - nm0);
            acc[nj][1] = __expf(acc[nj][1] - nm0);
            acc[nj][2] = __expf(acc[nj][2] - nm1);
            acc[nj][3] = __expf(acc[nj][3] - nm1);
            ts0 += acc[nj][0] + acc[nj][1];
            ts1 += acc[nj][2] + acc[nj][3];
        }
        ts0 += __shfl_xor_sync(0xffffffffu, ts0, 1);
        ts0 += __shfl_xor_sync(0xffffffffu, ts0, 2);
        ts1 += __shfl_xor_sync(0xffffffffu, ts1, 1);
        ts1 += __shfl_xor_sync(0xffffffffu, ts1, 2);
        l0 = l0 * c0 + ts0;  l1 = l1 * c1 + ts1;
        m0 = nm0;  m1 = nm1;
#pragma unroll
        for (int nj = 0; nj < 8; nj++) {
            o[nj][0] *= c0; o[nj][1] *= c0;
            o[nj][2] *= c1; o[nj][3] *= c1;
        }

        // ---- Pack P -> A-frags (bf16 hi/lo) ----
        uint32_t phi[4][4], plo[4][4];
#pragma unroll
        for (int kk2 = 0; kk2 < 4; kk2++) {
            phi[kk2][0] = pack_hilo(acc[2*kk2][0],   acc[2*kk2][1],   plo[kk2][0]);
            phi[kk2][1] = pack_hilo(acc[2*kk2][2],   acc[2*kk2][3],   plo[kk2][1]);
            phi[kk2][2] = pack_hilo(acc[2*kk2+1][0], acc[2*kk2+1][1], plo[kk2][2]);
            phi[kk2][3] = pack_hilo(acc[2*kk2+1][2], acc[2*kk2+1][3], plo[kk2][3]);
        }

        // ---- PV: O += P V (split precision, x2_trans V loads) ----
#pragma unroll
        for (int njd = 0; njd < 8; njd++) {
#pragma unroll
            for (int kk2 = 0; kk2 < 4; kk2++) {
                uint32_t vh[2], vl[2];
                uint32_t off = (uint32_t)((kk2 * 16 + (lane & 15)) * ATT_STRB + njd * 16);
                ldsm_x2_trans(vh, smem_base + T_VH + off);
                ldsm_x2_trans(vl, smem_base + T_VL + off);
                mma_bf16(o[njd], phi[kk2], vh[0], vh[1]);
                mma_bf16(o[njd], phi[kk2], vl[0], vl[1]);
                mma_bf16(o[njd], plo[kk2], vh[0], vh[1]);
            }
        }
        __syncthreads();   // protect V buffer + masks before next iter's issue
    }

    const int r0 = wid * 16 + (lane >> 2);
    if (!heavy) {
        const int s0 = qb * BLKSZ + r0;
        const int s1 = s0 + 8;
        float inv0 = from_mask[(size_t)b * SS + s0] / l0;
        float inv1 = from_mask[(size_t)b * SS + s1] / l1;
#pragma unroll
        for (int njd = 0; njd < 8; njd++) {
            const int col = njd * 8 + (lane & 3) * 2;
            {
                size_t idx = ((size_t)b * SS + s0) * DD + h * HDIM + col;
                uint32_t lo, hi = pack_hilo(o[njd][0] * inv0, o[njd][1] * inv0, lo);
                *(uint32_t*)(g_c_hi + idx) = hi;
                *(uint32_t*)(g_c_lo + idx) = lo;
            }
            {
                size_t idx = ((size_t)b * SS + s1) * DD + h * HDIM + col;
                uint32_t lo, hi = pack_hilo(o[njd][2] * inv1, o[njd][3] * inv1, lo);
                *(uint32_t*)(g_c_hi + idx) = hi;
                *(uint32_t*)(g_c_lo + idx) = lo;
            }
        }
    } else {
        const int cid = ((b * HH + h) * 2 + qb) * 8 + ch;
        float* pob = g_po + (size_t)cid * 4096;
#pragma unroll
        for (int njd = 0; njd < 8; njd++) {
            const int col = njd * 8 + (lane & 3) * 2;
            float2 s0v; s0v.x = o[njd][0]; s0v.y = o[njd][1];
            float2 s1v; s1v.x = o[njd][2]; s1v.y = o[njd][3];
            *(float2*)(pob + r0 * 64 + col) = s0v;
            *(float2*)(pob + (r0 + 8) * 64 + col) = s1v;
        }
        if ((lane & 3) == 0) {
            g_pm[cid * 64 + r0]     = m0;
            g_pm[cid * 64 + r0 + 8] = m1;
            g_pl[cid * 64 + r0]     = l0;
            g_pl[cid * 64 + r0 + 8] = l1;
        }
    }
}

// ---------------------------------------------------------------------------
// Combine split-KV partials for heavy q-blocks.
// ---------------------------------------------------------------------------
__global__ __launch_bounds__(128) void attn_combine(const float* __restrict__ from_mask)
{
    const int x  = blockIdx.x;
    const int qb = x & 1;
    const int h  = (x >> 1) & 15;
    const int b  = x >> 5;
    const int t  = threadIdx.x;
    const int r  = t >> 1;
    const int c0 = (t & 1) * 32;
    const int base8 = x * 8;

    float m[8], l[8], M = -1e30f;
#pragma unroll
    for (int i = 0; i < 8; i++) {
        m[i] = g_pm[(base8 + i) * 64 + r];
        l[i] = g_pl[(base8 + i) * 64 + r];
        M = fmaxf(M, m[i]);
    }
    float L = 0.f, sc[8];
#pragma unroll
    for (int i = 0; i < 8; i++) { sc[i] = __expf(m[i] - M); L += l[i] * sc[i]; }

    float acc[32];
#pragma unroll
    for (int c = 0; c < 32; c++) acc[c] = 0.f;
#pragma unroll
    for (int i = 0; i < 8; i++) {
        const float* p = g_po + (size_t)(base8 + i) * 4096 + r * 64 + c0;
        float s = sc[i];
#pragma unroll
        for (int c4 = 0; c4 < 8; c4++) {
            float4 v = *(const float4*)(p + c4 * 4);
            acc[c4*4+0] += s * v.x; acc[c4*4+1] += s * v.y;
            acc[c4*4+2] += s * v.z; acc[c4*4+3] += s * v.w;
        }
    }

    const int s_ = qb * BLKSZ + r;
    float inv = from_mask[(size_t)b * SS + s_] / L;
    size_t idx = ((size_t)b * SS + s_) * DD + h * HDIM + c0;
#pragma unroll
    for (int c = 0; c < 32; c += 2) {
        uint32_t lo, hi = pack_hilo(acc[c] * inv, acc[c+1] * inv, lo);
        *(uint32_t*)(g_c_hi + idx + c) = hi;
        *(uint32_t*)(g_c_lo + idx + c) = lo;
    }
}

// ---------------------------------------------------------------------------
extern "C" void kernel_launch(void* const* d_in, const int* in_sizes, int n_in,
                              void* d_out, int out_size)
{
    const float* tokens    = (const float*)d_in[0];
    const float* band_mask = (const float*)d_in[1];
    const float* from_mask = (const float*)d_in[2];
    const float* to_mask   = (const float*)d_in[3];
    const float* Wq        = (const float*)d_in[4];
    const float* Wk        = (const float*)d_in[5];
    const float* Wv        = (const float*)d_in[6];
    const float* Wu        = (const float*)d_in[7];
    const float* bu        = (const float*)d_in[8];
    float* out = (float*)d_out;

    cudaFuncSetAttribute(attn_kernel,
                         cudaFuncAttributeMaxDynamicSharedMemorySize, ATTN_SMEM_BYTES);
    cudaFuncSetAttribute(gemm_hmma_kernel,
                         cudaFuncAttributeMaxDynamicSharedMemorySize, GEMM_SMEM_BYTES);

    // 0) Precision-split inputs and weights
    split_x_kernel<<<(MROWS * DD / 4) / 256, 256>>>(tokens);
    wsplit_kernel<<<dim3(1024, 4), 256>>>(Wq, Wk, Wv, Wu);

    // 1) QKV projections (double-buffered HMMA, grid.z = q/k/v)
    gemm_hmma_kernel<<<dim3(8, 64, 3), 256, GEMM_SMEM_BYTES>>>(0, nullptr, nullptr);

    // 2) Sparse attention (light + split-KV heavy in one grid, cp.async pipelined)
    attn_kernel<<<dim3(78, HH, BB), 128, ATTN_SMEM_BYTES>>>(band_mask, from_mask, to_mask);

    // 2b) Combine heavy partials
    attn_combine<<<64, 128>>>(from_mask);

    // 3) Output projection + bias (double-buffered HMMA)
    gemm_hmma_kernel<<<dim3(8, 64, 1), 256, GEMM_SMEM_BYTES>>>(3, bu, out);
}

// round 9
// speedup vs baseline: 1.4926x; 1.0262x over previous
#include <cuda_runtime.h>
#include <cuda_bf16.h>
#include <cstdint>
#include <math.h>

#define BB 2
#define SS 4096
#define DD 1024
#define HH 16
#define BLKSZ 64
#define NB 64          // S / BLK
#define NGB 2          // G / BLK
#define HDIM 64        // D / H
#define MROWS (BB*SS)  // 8192

// ---------------------------------------------------------------------------
// Device scratch (no allocation allowed)
// ---------------------------------------------------------------------------
__device__ __nv_bfloat16 g_x_hi[(size_t)MROWS*DD];
__device__ __nv_bfloat16 g_x_lo[(size_t)MROWS*DD];
__device__ __nv_bfloat16 g_c_hi[(size_t)MROWS*DD];
__device__ __nv_bfloat16 g_c_lo[(size_t)MROWS*DD];
__device__ __nv_bfloat16 g_w_hi[(size_t)4*DD*DD];   // [w][k][n] (native layout)
__device__ __nv_bfloat16 g_w_lo[(size_t)4*DD*DD];
// Q/K/V head-split bf16 hi/lo: [b,h,s,64]
__device__ __nv_bfloat16 g_qh[(size_t)BB*HH*SS*HDIM];
__device__ __nv_bfloat16 g_ql[(size_t)BB*HH*SS*HDIM];
__device__ __nv_bfloat16 g_kh[(size_t)BB*HH*SS*HDIM];
__device__ __nv_bfloat16 g_kl[(size_t)BB*HH*SS*HDIM];
__device__ __nv_bfloat16 g_vh[(size_t)BB*HH*SS*HDIM];
__device__ __nv_bfloat16 g_vl[(size_t)BB*HH*SS*HDIM];
// split-KV partials for heavy q-blocks
__device__ float g_po[(size_t)512*4096];
__device__ float g_pm[512*64];
__device__ float g_pl[512*64];

// ---------------------------------------------------------------------------
// mma.sync / ldmatrix / cp.async helpers (generic sm_80+ PTX)
// ---------------------------------------------------------------------------
__device__ __forceinline__ uint32_t smem_u32(const void* p) {
    uint32_t a;
    asm("{ .reg .u64 t; cvta.to.shared.u64 t, %1; cvt.u32.u64 %0, t; }" : "=r"(a) : "l"(p));
    return a;
}
__device__ __forceinline__ void ldsm_x4(uint32_t* r, uint32_t addr) {
    asm volatile("ldmatrix.sync.aligned.m8n8.x4.shared.b16 {%0,%1,%2,%3}, [%4];"
        : "=r"(r[0]), "=r"(r[1]), "=r"(r[2]), "=r"(r[3]) : "r"(addr));
}
__device__ __forceinline__ void ldsm_x2_trans(uint32_t* r, uint32_t addr) {
    asm volatile("ldmatrix.sync.aligned.m8n8.x2.trans.shared.b16 {%0,%1}, [%2];"
        : "=r"(r[0]), "=r"(r[1]) : "r"(addr));
}
__device__ __forceinline__ void mma_bf16(float (&c)[4], const uint32_t* a,
                                         uint32_t b0, uint32_t b1) {
    asm volatile("mma.sync.aligned.m16n8k16.row.col.f32.bf16.bf16.f32 "
        "{%0,%1,%2,%3}, {%4,%5,%6,%7}, {%8,%9}, {%0,%1,%2,%3};"
        : "+f"(c[0]), "+f"(c[1]), "+f"(c[2]), "+f"(c[3])
        : "r"(a[0]), "r"(a[1]), "r"(a[2]), "r"(a[3]), "r"(b0), "r"(b1));
}
__device__ __forceinline__ void cp_async16(uint32_t saddr, const void* gptr) {
    asm volatile("cp.async.cg.shared.global [%0], [%1], 16;" :: "r"(saddr), "l"(gptr));
}
#define CP_COMMIT asm volatile("cp.async.commit_group;")
#define CP_WAIT2  asm volatile("cp.async.wait_group 2;")
#define CP_WAIT1  asm volatile("cp.async.wait_group 1;")
#define CP_WAIT0  asm volatile("cp.async.wait_group 0;")

// pack two floats -> bf16x2 hi, bf16x2 lo (residual)
__device__ __forceinline__ uint32_t pack_hilo(float a, float b, uint32_t& lo_out) {
    __nv_bfloat162 h; h.x = __float2bfloat16(a); h.y = __float2bfloat16(b);
    __nv_bfloat162 l;
    l.x = __float2bfloat16(a - __bfloat162float(h.x));
    l.y = __float2bfloat16(b - __bfloat162float(h.y));
    lo_out = *(uint32_t*)&l;
    return *(uint32_t*)&h;
}

// ---------------------------------------------------------------------------
// Split tokens into bf16 hi/lo
// ---------------------------------------------------------------------------
__global__ __launch_bounds__(256) void split_x_kernel(const float* __restrict__ X)
{
    size_t i = (size_t)blockIdx.x * 256 + threadIdx.x;
    float4 v = ((const float4*)X)[i];
    float vs[4] = {v.x, v.y, v.z, v.w};
#pragma unroll
    for (int j = 0; j < 4; j++) {
        __nv_bfloat16 hi = __float2bfloat16(vs[j]);
        float lo = vs[j] - __bfloat162float(hi);
        g_x_hi[i * 4 + j] = hi;
        g_x_lo[i * 4 + j] = __float2bfloat16(lo);
    }
}

// ---------------------------------------------------------------------------
// Elementwise weight split
// ---------------------------------------------------------------------------
__global__ __launch_bounds__(256) void wsplit_kernel(
    const float* __restrict__ Wq, const float* __restrict__ Wk,
    const float* __restrict__ Wv, const float* __restrict__ Wu)
{
    const int w = blockIdx.y;
    const float* W = (w == 0) ? Wq : (w == 1) ? Wk : (w == 2) ? Wv : Wu;
    size_t i = (size_t)blockIdx.x * 256 + threadIdx.x;
    float4 v = ((const float4*)W)[i];
    float vs[4] = {v.x, v.y, v.z, v.w};
    size_t base = (size_t)w * DD * DD + i * 4;
#pragma unroll
    for (int j = 0; j < 4; j++) {
        __nv_bfloat16 hi = __float2bfloat16(vs[j]);
        float lo = vs[j] - __bfloat162float(hi);
        g_w_hi[base + j] = hi;
        g_w_lo[base + j] = __float2bfloat16(lo);
    }
}

// ---------------------------------------------------------------------------
// Split-bf16 HMMA GEMM, 3-stage cp.async pipeline (x2.trans B loads kept).
// CTA 128x128, K-chunk 32. One __syncthreads per chunk; prefetch distance 2.
// mode 0/1/2: out = bf16 hi/lo head-split q/k/v;  mode 3: fp32 out + bias.
// ---------------------------------------------------------------------------
#define GK 32
#define SA2 40            // A stride (b16): 32 + 8 pad
#define SB2 136           // B stride (b16)
#define SA_HI_B 0
#define SA_LO_B 10240     // 128*40*2
#define SB_HI_B 20480
#define SB_LO_B 29184
#define STAGE_B 37888
#define NSTAGE 3
#define GEMM_SMEM_BYTES (NSTAGE*STAGE_B)

__global__ __launch_bounds__(256, 2) void gemm_hmma_kernel(
    int mode_base, const float* __restrict__ bias, float* __restrict__ out_ptr)
{
    extern __shared__ __align__(16) char gsm[];
    const uint32_t smem_base = smem_u32(gsm);

    const int t    = threadIdx.x;
    const int lane = t & 31;
    const int wid  = t >> 5;
    const int wm   = wid & 3;
    const int wn   = wid >> 2;
    const int mode = mode_base + blockIdx.z;

    const int n0 = blockIdx.x * 128;
    const int m0 = blockIdx.y * 128;

    const __nv_bfloat16* Ahi = (mode < 3) ? g_x_hi : g_c_hi;
    const __nv_bfloat16* Alo = (mode < 3) ? g_x_lo : g_c_lo;
    const __nv_bfloat16* Bhi = g_w_hi + (size_t)mode * DD * DD;
    const __nv_bfloat16* Blo = g_w_lo + (size_t)mode * DD * DD;

    float acc[2][8][4];
#pragma unroll
    for (int mi = 0; mi < 2; mi++)
#pragma unroll
        for (int nj = 0; nj < 8; nj++)
#pragma unroll
            for (int e = 0; e < 4; e++) acc[mi][nj][e] = 0.f;

    const int lrow = lane & 15;
    const int lcol = (lane >> 4) * 8;

    const int arow0 = t >> 2,          aseg0 = (t & 3) * 8;
    const int arow1 = (t + 256) >> 2,  aseg1 = ((t + 256) & 3) * 8;
    const int brow0 = t >> 4,          bseg0 = (t & 15) * 8;
    const int brow1 = (t + 256) >> 4,  bseg1 = ((t + 256) & 15) * 8;

#define GEMM_PREFETCH(KC, SBUF) do {                                        \
    const int k0_ = (KC) * GK;                                              \
    const uint32_t sb_ = smem_base + (uint32_t)(SBUF) * STAGE_B;            \
    {   size_t go = (size_t)(m0 + arow0) * DD + k0_ + aseg0;                \
        uint32_t so = sb_ + (uint32_t)(arow0 * SA2 + aseg0) * 2;            \
        cp_async16(so + SA_HI_B, Ahi + go);                                 \
        cp_async16(so + SA_LO_B, Alo + go); }                               \
    {   size_t go = (size_t)(m0 + arow1) * DD + k0_ + aseg1;                \
        uint32_t so = sb_ + (uint32_t)(arow1 * SA2 + aseg1) * 2;            \
        cp_async16(so + SA_HI_B, Ahi + go);                                 \
        cp_async16(so + SA_LO_B, Alo + go); }                               \
    {   size_t go = (size_t)(k0_ + brow0) * DD + n0 + bseg0;                \
        uint32_t so = sb_ + (uint32_t)(brow0 * SB2 + bseg0) * 2;            \
        cp_async16(so + SB_HI_B, Bhi + go);                                 \
        cp_async16(so + SB_LO_B, Blo + go); }                               \
    {   size_t go = (size_t)(k0_ + brow1) * DD + n0 + bseg1;                \
        uint32_t so = sb_ + (uint32_t)(brow1 * SB2 + bseg1) * 2;            \
        cp_async16(so + SB_HI_B, Bhi + go);                                 \
        cp_async16(so + SB_LO_B, Blo + go); }                               \
    CP_COMMIT; } while (0)

    GEMM_PREFETCH(0, 0);
    GEMM_PREFETCH(1, 1);

    int cs = 0;          // compute buffer index for kc
    int ps = 2;          // prefetch buffer index for kc+2
    for (int kc = 0; kc < 32; kc++) {
        if (kc <= 29) { CP_WAIT1; } else { CP_WAIT0; }
        __syncthreads();
        if (kc + 2 < 32) {
            GEMM_PREFETCH(kc + 2, ps);
            ps = (ps + 1 == NSTAGE) ? 0 : ps + 1;
        }

        const uint32_t sb = smem_base + (uint32_t)cs * STAGE_B;
        cs = (cs + 1 == NSTAGE) ? 0 : cs + 1;
#pragma unroll
        for (int kk = 0; kk < 2; kk++) {
            uint32_t ah[2][4], al[2][4];
#pragma unroll
            for (int mi = 0; mi < 2; mi++) {
                uint32_t off = (uint32_t)((wm * 32 + mi * 16 + lrow) * SA2 + kk * 16 + lcol) * 2;
                ldsm_x4(ah[mi], sb + SA_HI_B + off);
                ldsm_x4(al[mi], sb + SA_LO_B + off);
            }
            uint32_t bh[8][2], bl[8][2];
#pragma unroll
            for (int nj = 0; nj < 8; nj++) {
                uint32_t off = (uint32_t)((kk * 16 + lrow) * SB2 + wn * 64 + nj * 8) * 2;
                ldsm_x2_trans(bh[nj], sb + SB_HI_B + off);
                ldsm_x2_trans(bl[nj], sb + SB_LO_B + off);
            }
#pragma unroll
            for (int mi = 0; mi < 2; mi++)
#pragma unroll
                for (int nj = 0; nj < 8; nj++) {
                    mma_bf16(acc[mi][nj], ah[mi], bh[nj][0], bh[nj][1]);
                    mma_bf16(acc[mi][nj], ah[mi], bl[nj][0], bl[nj][1]);
                    mma_bf16(acc[mi][nj], al[mi], bh[nj][0], bh[nj][1]);
                }
        }
    }

    // Epilogue (register-only sources; no smem hazard)
#pragma unroll
    for (int mi = 0; mi < 2; mi++) {
        const int r0 = m0 + wm * 32 + mi * 16 + (lane >> 2);
#pragma unroll
        for (int nj = 0; nj < 8; nj++) {
            const int col = wn * 64 + nj * 8 + (lane & 3) * 2;
            if (mode < 3) {
                __nv_bfloat16* Oh = (mode == 0) ? g_qh : (mode == 1) ? g_kh : g_vh;
                __nv_bfloat16* Ol = (mode == 0) ? g_ql : (mode == 1) ? g_kl : g_vl;
                const int h  = (n0 + col) >> 6;
                const int dd = col & 63;
#pragma unroll
                for (int half = 0; half < 2; half++) {
                    int r = r0 + half * 8;
                    int b_ = r >> 12, s = r & 4095;
                    float a0 = acc[mi][nj][half * 2 + 0];
                    float a1 = acc[mi][nj][half * 2 + 1];
                    uint32_t lo, hi = pack_hilo(a0, a1, lo);
                    size_t idx = (((size_t)(b_ * HH + h)) * SS + s) * HDIM + dd;
                    *(uint32_t*)(Oh + idx) = hi;
                    *(uint32_t*)(Ol + idx) = lo;
                }
            } else {
                float bv0 = bias[n0 + col], bv1 = bias[n0 + col + 1];
                float2 st0; st0.x = acc[mi][nj][0] + bv0; st0.y = acc[mi][nj][1] + bv1;
                float2 st1; st1.x = acc[mi][nj][2] + bv0; st1.y = acc[mi][nj][3] + bv1;
                *(float2*)(out_ptr + (size_t)r0 * DD + n0 + col) = st0;
                *(float2*)(out_ptr + (size_t)(r0 + 8) * DD + n0 + col) = st1;
            }
        }
    }
}

// ---------------------------------------------------------------------------
// BigBird sparse attention on HMMA, split-KV heavy blocks, cp.async pipelined
// (unchanged from R8 / proven state).
// ---------------------------------------------------------------------------
#define ATT_STRB 144                  // 72 b16 row stride, in bytes
#define KSTAGE(s) ((s) * 18432)       // per stage: KH +0, KL +9216
#define T_VH 36864
#define T_VL 46080
#define T_PEN2 55296                  // raw band_mask floats, 64 x 68 (stride 272B)
#define T_PEN1 72704                  // raw to_mask slice, 64 floats
#define ATTN_SMEM_BYTES 72976

__global__ __launch_bounds__(128, 3) void attn_kernel(
    const float* __restrict__ band_mask,
    const float* __restrict__ from_mask,
    const float* __restrict__ to_mask)
{
    extern __shared__ __align__(16) char smraw[];
    const uint32_t smem_base = smem_u32(smraw);
    const float* pen2f = (const float*)(smraw + T_PEN2);
    const float* pen1f = (const float*)(smraw + T_PEN1);

    const int bx = blockIdx.x;
    const int h  = blockIdx.y;
    const int b  = blockIdx.z;
    const int t  = threadIdx.x;
    const int lane = t & 31;
    const int wid  = t >> 5;

    const bool heavy = (bx >= 62);
    int qb, ch = 0;
    if (heavy) { int hx = bx - 62; qb = hx >> 3; ch = hx & 7; }
    else qb = bx + 2;

    const float rs  = 0.125f;
    const float pen = -10000.f;
    const size_t bh64 = ((size_t)(b * HH + h)) * SS * HDIM;

    // ---- Load Q tile (hi/lo) into K-stage-0 area, extract frags ----
    {
        const __nv_bfloat16* qhp = g_qh + bh64 + (size_t)qb * BLKSZ * HDIM;
        const __nv_bfloat16* qlp = g_ql + bh64 + (size_t)qb * BLKSZ * HDIM;
        for (int i = t; i < 512; i += 128) {
            int row = i >> 3, seg = (i & 7) * 8;
            *(uint4*)(smraw + row * ATT_STRB + seg * 2)        = *(const uint4*)(qhp + row * HDIM + seg);
            *(uint4*)(smraw + 9216 + row * ATT_STRB + seg * 2) = *(const uint4*)(qlp + row * HDIM + seg);
        }
    }
    __syncthreads();

    uint32_t qfh[4][4], qfl[4][4];
    {
        const int lrow = lane & 15;
        const int lcol = (lane >> 4) * 8;
#pragma unroll
        for (int kk = 0; kk < 4; kk++) {
            uint32_t off = (uint32_t)((wid * 16 + lrow) * ATT_STRB + (kk * 16 + lcol) * 2);
            ldsm_x4(qfh[kk], smem_base + off);
            ldsm_x4(qfl[kk], smem_base + 9216 + off);
        }
    }
    __syncthreads();   // everyone done reading Q before K(0) cp.async overwrites

    // ---- schedule ----
    int nt;
    int kbs[5];
    bool is_band = false;
    if (heavy) {
        nt = 8;
    } else if (qb == NGB) {
        nt = 5; kbs[0]=0; kbs[1]=1; kbs[2]=2; kbs[3]=3; kbs[4]=4;
    } else if (qb == NB - 1) {
        nt = 5; kbs[0]=0; kbs[1]=1; kbs[2]=61; kbs[3]=62; kbs[4]=63;
    } else {
        nt = 5; kbs[0]=0; kbs[1]=1; kbs[2]=qb-1; kbs[3]=qb; kbs[4]=qb+1; is_band = true;
    }

#define KB_OF(IT) (heavy ? (ch * 8 + (IT)) : kbs[(IT)])

    // ---- cp.async issue helpers ----
#define ISSUE_K(KB, STG) do {                                               \
    const __nv_bfloat16* khp_ = g_kh + bh64 + (size_t)(KB) * BLKSZ * HDIM;  \
    const __nv_bfloat16* klp_ = g_kl + bh64 + (size_t)(KB) * BLKSZ * HDIM;  \
    for (int i = t; i < 512; i += 128) {                                    \
        int row = i >> 3, seg = (i & 7) * 8;                                \
        uint32_t so = smem_base + KSTAGE(STG) + row * ATT_STRB + seg * 2;   \
        cp_async16(so,        khp_ + row * HDIM + seg);                     \
        cp_async16(so + 9216, klp_ + row * HDIM + seg);                     \
    }                                                                       \
    CP_COMMIT; } while (0)

#define ISSUE_VP(IT, KB, BANDT) do {                                        \
    const __nv_bfloat16* vhp_ = g_vh + bh64 + (size_t)(KB) * BLKSZ * HDIM;  \
    const __nv_bfloat16* vlp_ = g_vl + bh64 + (size_t)(KB) * BLKSZ * HDIM;  \
    for (int i = t; i < 512; i += 128) {                                    \
        int row = i >> 3, seg = (i & 7) * 8;                                \
        uint32_t so = smem_base + T_VH + row * ATT_STRB + seg * 2;          \
        cp_async16(so,        vhp_ + row * HDIM + seg);                     \
        cp_async16(so + 9216, vlp_ + row * HDIM + seg);                     \
    }                                                                       \
    if (BANDT) {                                                            \
        const float* bmb_ = band_mask                                       \
            + ((size_t)(b * 60 + (qb - 3)) * 64) * 192 + (size_t)((IT) - 2) * 64; \
        for (int i = t; i < 1024; i += 128) {                               \
            int row = i >> 4, c = i & 15;                                   \
            cp_async16(smem_base + T_PEN2 + row * 272 + c * 16,             \
                       bmb_ + row * 192 + c * 4);                           \
        }                                                                   \
    } else if (t < 16) {                                                    \
        cp_async16(smem_base + T_PEN1 + t * 16,                             \
                   to_mask + (size_t)b * SS + (KB) * BLKSZ + t * 4);        \
    }                                                                       \
    CP_COMMIT; } while (0)

    // ---- flash state ----
    float m0 = -1e30f, m1 = -1e30f, l0 = 0.f, l1 = 0.f;
    float o[8][4];
#pragma unroll
    for (int nj = 0; nj < 8; nj++)
#pragma unroll
        for (int e = 0; e < 4; e++) o[nj][e] = 0.f;

    // prologue: K(0) -> stage 0
    ISSUE_K(KB_OF(0), 0);

    for (int it = 0; it < nt; it++) {
        const int kb = KB_OF(it);
        const bool band_tile = (is_band && it >= 2);

        ISSUE_VP(it, kb, band_tile);
        if (it + 1 < nt) {
            ISSUE_K(KB_OF(it + 1), (it + 1) & 1);
            CP_WAIT2;            // K(it) landed (VP(it), K(it+1) may be pending)
        } else {
            CP_WAIT1;            // K(it) landed (VP(it) may be pending)
        }
        __syncthreads();

        // ---- Scores: S = Q K^T (split precision), K from stage it&1 ----
        const uint32_t kst = smem_base + KSTAGE(it & 1);
        float acc[8][4];
#pragma unroll
        for (int nj = 0; nj < 8; nj++)
#pragma unroll
            for (int e = 0; e < 4; e++) acc[nj][e] = 0.f;

#pragma unroll
        for (int nj = 0; nj < 8; nj++) {
            uint32_t kh8[8], kl8[8];
            uint32_t rbase = (uint32_t)((nj * 8 + (lane & 7)) * ATT_STRB + (lane >> 3) * 16);
            ldsm_x4(kh8,     kst + rbase);
            ldsm_x4(kh8 + 4, kst + rbase + 64);
            ldsm_x4(kl8,     kst + 9216 + rbase);
            ldsm_x4(kl8 + 4, kst + 9216 + rbase + 64);
#pragma unroll
            for (int kk = 0; kk < 4; kk++) {
                mma_bf16(acc[nj], qfh[kk], kh8[2*kk], kh8[2*kk+1]);
                mma_bf16(acc[nj], qfh[kk], kl8[2*kk], kl8[2*kk+1]);
                mma_bf16(acc[nj], qfl[kk], kh8[2*kk], kh8[2*kk+1]);
            }
        }

        // ---- V + mask data ready? ----
        if (it + 1 < nt) { CP_WAIT1; } else { CP_WAIT0; }
        __syncthreads();

        // ---- Scale + mask ((1-m)*pen computed inline from raw masks) ----
        const int qr0 = wid * 16 + (lane >> 2);
#pragma unroll
        for (int nj = 0; nj < 8; nj++) {
#pragma unroll
            for (int e = 0; e < 4; e++) {
                int col = nj * 8 + (lane & 3) * 2 + (e & 1);
                float mv = band_tile
                    ? pen2f[(qr0 + (e >> 1) * 8) * 68 + col]
                    : pen1f[col];
                acc[nj][e] = acc[nj][e] * rs + (1.f - mv) * pen;
            }
        }

        // ---- Streaming softmax ----
        float tm0 = -1e30f, tm1 = -1e30f;
#pragma unroll
        for (int nj = 0; nj < 8; nj++) {
            tm0 = fmaxf(tm0, fmaxf(acc[nj][0], acc[nj][1]));
            tm1 = fmaxf(tm1, fmaxf(acc[nj][2], acc[nj][3]));
        }
        tm0 = fmaxf(tm0, __shfl_xor_sync(0xffffffffu, tm0, 1));
        tm0 = fmaxf(tm0, __shfl_xor_sync(0xffffffffu, tm0, 2));
        tm1 = fmaxf(tm1, __shfl_xor_sync(0xffffffffu, tm1, 1));
        tm1 = fmaxf(tm1, __shfl_xor_sync(0xffffffffu, tm1, 2));

        float nm0 = fmaxf(m0, tm0), nm1 = fmaxf(m1, tm1);
        float c0 = __expf(m0 - nm0), c1 = __expf(m1 - nm1);
        float ts0 = 0.f, ts1 = 0.f;
#pragma unroll
        for (int nj = 0; nj < 8; nj++) {
            acc[nj][0] = __expf(acc[nj][0] - nm0);
            acc[nj][1] = __expf(acc[nj][1] - nm0);
            acc[nj][2] = __expf(acc[nj][2] - nm1);
            acc[nj][3] = __expf(acc[nj][3] - nm1);
            ts0 += acc[nj][0] + acc[nj][1];
            ts1 += acc[nj][2] + acc[nj][3];
        }
        ts0 += __shfl_xor_sync(0xffffffffu, ts0, 1);
        ts0 += __shfl_xor_sync(0xffffffffu, ts0, 2);
        ts1 += __shfl_xor_sync(0xffffffffu, ts1, 1);
        ts1 += __shfl_xor_sync(0xffffffffu, ts1, 2);
        l0 = l0 * c0 + ts0;  l1 = l1 * c1 + ts1;
        m0 = nm0;  m1 = nm1;
#pragma unroll
        for (int nj = 0; nj < 8; nj++) {
            o[nj][0] *= c0; o[nj][1] *= c0;
            o[nj][2] *= c1; o[nj][3] *= c1;
        }

        // ---- Pack P -> A-frags (bf16 hi/lo) ----
        uint32_t phi[4][4], plo[4][4];
#pragma unroll
        for (int kk2 = 0; kk2 < 4; kk2++) {
            phi[kk2][0] = pack_hilo(acc[2*kk2][0],   acc[2*kk2][1],   plo[kk2][0]);
            phi[kk2][1] = pack_hilo(acc[2*kk2][2],   acc[2*kk2][3],   plo[kk2][1]);
            phi[kk2][2] = pack_hilo(acc[2*kk2+1][0], acc[2*kk2+1][1], plo[kk2][2]);
            phi[kk2][3] = pack_hilo(acc[2*kk2+1][2], acc[2*kk2+1][3], plo[kk2][3]);
        }

        // ---- PV: O += P V (split precision, x2_trans V loads) ----
#pragma unroll
        for (int njd = 0; njd < 8; njd++) {
#pragma unroll
            for (int kk2 = 0; kk2 < 4; kk2++) {
                uint32_t vh[2], vl[2];
                uint32_t off = (uint32_t)((kk2 * 16 + (lane & 15)) * ATT_STRB + njd * 16);
                ldsm_x2_trans(vh, smem_base + T_VH + off);
                ldsm_x2_trans(vl, smem_base + T_VL + off);
                mma_bf16(o[njd], phi[kk2], vh[0], vh[1]);
                mma_bf16(o[njd], phi[kk2], vl[0], vl[1]);
                mma_bf16(o[njd], plo[kk2], vh[0], vh[1]);
            }
        }
        __syncthreads();   // protect V buffer + masks before next iter's issue
    }

    const int r0 = wid * 16 + (lane >> 2);
    if (!heavy) {
        const int s0 = qb * BLKSZ + r0;
        const int s1 = s0 + 8;
        float inv0 = from_mask[(size_t)b * SS + s0] / l0;
        float inv1 = from_mask[(size_t)b * SS + s1] / l1;
#pragma unroll
        for (int njd = 0; njd < 8; njd++) {
            const int col = njd * 8 + (lane & 3) * 2;
            {
                size_t idx = ((size_t)b * SS + s0) * DD + h * HDIM + col;
                uint32_t lo, hi = pack_hilo(o[njd][0] * inv0, o[njd][1] * inv0, lo);
                *(uint32_t*)(g_c_hi + idx) = hi;
                *(uint32_t*)(g_c_lo + idx) = lo;
            }
            {
                size_t idx = ((size_t)b * SS + s1) * DD + h * HDIM + col;
                uint32_t lo, hi = pack_hilo(o[njd][2] * inv1, o[njd][3] * inv1, lo);
                *(uint32_t*)(g_c_hi + idx) = hi;
                *(uint32_t*)(g_c_lo + idx) = lo;
            }
        }
    } else {
        const int cid = ((b * HH + h) * 2 + qb) * 8 + ch;
        float* pob = g_po + (size_t)cid * 4096;
#pragma unroll
        for (int njd = 0; njd < 8; njd++) {
            const int col = njd * 8 + (lane & 3) * 2;
            float2 s0v; s0v.x = o[njd][0]; s0v.y = o[njd][1];
            float2 s1v; s1v.x = o[njd][2]; s1v.y = o[njd][3];
            *(float2*)(pob + r0 * 64 + col) = s0v;
            *(float2*)(pob + (r0 + 8) * 64 + col) = s1v;
        }
        if ((lane & 3) == 0) {
            g_pm[cid * 64 + r0]     = m0;
            g_pm[cid * 64 + r0 + 8] = m1;
            g_pl[cid * 64 + r0]     = l0;
            g_pl[cid * 64 + r0 + 8] = l1;
        }
    }
}

// ---------------------------------------------------------------------------
// Combine split-KV partials for heavy q-blocks.
// ---------------------------------------------------------------------------
__global__ __launch_bounds__(128) void attn_combine(const float* __restrict__ from_mask)
{
    const int x  = blockIdx.x;
    const int qb = x & 1;
    const int h  = (x >> 1) & 15;
    const int b  = x >> 5;
    const int t  = threadIdx.x;
    const int r  = t >> 1;
    const int c0 = (t & 1) * 32;
    const int base8 = x * 8;

    float m[8], l[8], M = -1e30f;
#pragma unroll
    for (int i = 0; i < 8; i++) {
        m[i] = g_pm[(base8 + i) * 64 + r];
        l[i] = g_pl[(base8 + i) * 64 + r];
        M = fmaxf(M, m[i]);
    }
    float L = 0.f, sc[8];
#pragma unroll
    for (int i = 0; i < 8; i++) { sc[i] = __expf(m[i] - M); L += l[i] * sc[i]; }

    float acc[32];
#pragma unroll
    for (int c = 0; c < 32; c++) acc[c] = 0.f;
#pragma unroll
    for (int i = 0; i < 8; i++) {
        const float* p = g_po + (size_t)(base8 + i) * 4096 + r * 64 + c0;
        float s = sc[i];
#pragma unroll
        for (int c4 = 0; c4 < 8; c4++) {
            float4 v = *(const float4*)(p + c4 * 4);
            acc[c4*4+0] += s * v.x; acc[c4*4+1] += s * v.y;
            acc[c4*4+2] += s * v.z; acc[c4*4+3] += s * v.w;
        }
    }

    const int s_ = qb * BLKSZ + r;
    float inv = from_mask[(size_t)b * SS + s_] / L;
    size_t idx = ((size_t)b * SS + s_) * DD + h * HDIM + c0;
#pragma unroll
    for (int c = 0; c < 32; c += 2) {
        uint32_t lo, hi = pack_hilo(acc[c] * inv, acc[c+1] * inv, lo);
        *(uint32_t*)(g_c_hi + idx + c) = hi;
        *(uint32_t*)(g_c_lo + idx + c) = lo;
    }
}

// ---------------------------------------------------------------------------
extern "C" void kernel_launch(void* const* d_in, const int* in_sizes, int n_in,
                              void* d_out, int out_size)
{
    const float* tokens    = (const float*)d_in[0];
    const float* band_mask = (const float*)d_in[1];
    const float* from_mask = (const float*)d_in[2];
    const float* to_mask   = (const float*)d_in[3];
    const float* Wq        = (const float*)d_in[4];
    const float* Wk        = (const float*)d_in[5];
    const float* Wv        = (const float*)d_in[6];
    const float* Wu        = (const float*)d_in[7];
    const float* bu        = (const float*)d_in[8];
    float* out = (float*)d_out;

    cudaFuncSetAttribute(attn_kernel,
                         cudaFuncAttributeMaxDynamicSharedMemorySize, ATTN_SMEM_BYTES);
    cudaFuncSetAttribute(gemm_hmma_kernel,
                         cudaFuncAttributeMaxDynamicSharedMemorySize, GEMM_SMEM_BYTES);

    // 0) Precision-split inputs and weights
    split_x_kernel<<<(MROWS * DD / 4) / 256, 256>>>(tokens);
    wsplit_kernel<<<dim3(1024, 4), 256>>>(Wq, Wk, Wv, Wu);

    // 1) QKV projections (3-stage pipelined HMMA, grid.z = q/k/v)
    gemm_hmma_kernel<<<dim3(8, 64, 3), 256, GEMM_SMEM_BYTES>>>(0, nullptr, nullptr);

    // 2) Sparse attention (light + split-KV heavy in one grid, cp.async pipelined)
    attn_kernel<<<dim3(78, HH, BB), 128, ATTN_SMEM_BYTES>>>(band_mask, from_mask, to_mask);

    // 2b) Combine heavy partials
    attn_combine<<<64, 128>>>(from_mask);

    // 3) Output projection + bias (3-stage pipelined HMMA)
    gemm_hmma_kernel<<<dim3(8, 64, 1), 256, GEMM_SMEM_BYTES>>>(3, bu, out);
}